// round 9
// baseline (speedup 1.0000x reference)
#include <cuda_runtime.h>
#include <cstdint>
#include <math.h>

// ===========================================================================
// MMFConv2d sm_103a (base-target-safe), Round 9:
//   K1: per-pixel channel-LN + int8 quant -> s8 NHWC + fp32 inv_s (R6-proven)
//   K2: ternary weight quant -> s8 [tap][co][ci] (R6-proven)
//   K3: conv = 9 per-tap s8 IMMA GEMMs (m16n8k32, fresh s32 acc per tap),
//       fp32 accumulation weighted by per-INPUT-pixel inv_s (correct scaling),
//       R8-proven strip/row-ring/tap-phased-prefetch skeleton, 8 warps 64x64.
// ===========================================================================

__device__ unsigned char g_a8[(size_t)8 * 65536 * 64];   // s8 NHWC
__device__ float g_invs[8 * 65536];                      // per-pixel inv_s
__device__ char  g_w8[9 * 64 * 64];                      // [tap][co][ci]
__device__ float g_inv_sw;

// ---------------------------------------------------------------------------
__device__ __forceinline__ uint32_t smem_u32(const void* p) {
    uint32_t a;
    asm("{ .reg .u64 t; cvta.to.shared.u64 t, %1; cvt.u32.u64 %0, t; }"
        : "=r"(a) : "l"(p));
    return a;
}
__device__ __forceinline__ void ldsm_x4(uint32_t (&r)[4], uint32_t a) {
    asm volatile("ldmatrix.sync.aligned.m8n8.x4.shared.b16 {%0,%1,%2,%3}, [%4];"
                 : "=r"(r[0]), "=r"(r[1]), "=r"(r[2]), "=r"(r[3]) : "r"(a));
}
__device__ __forceinline__ void ldsm_x2(uint32_t (&r)[2], uint32_t a) {
    asm volatile("ldmatrix.sync.aligned.m8n8.x2.shared.b16 {%0,%1}, [%2];"
                 : "=r"(r[0]), "=r"(r[1]) : "r"(a));
}
// D = A*B (zero C)
__device__ __forceinline__ void imma_z(int (&d)[4], const uint32_t (&a)[4],
                                       const uint32_t (&b)[2]) {
    asm volatile(
        "mma.sync.aligned.m16n8k32.row.col.s32.s8.s8.s32 "
        "{%0,%1,%2,%3}, {%4,%5,%6,%7}, {%8,%9}, {%10,%10,%10,%10};"
        : "=r"(d[0]), "=r"(d[1]), "=r"(d[2]), "=r"(d[3])
        : "r"(a[0]), "r"(a[1]), "r"(a[2]), "r"(a[3]), "r"(b[0]), "r"(b[1]),
          "r"(0));
}
// D += A*B
__device__ __forceinline__ void imma(int (&d)[4], const uint32_t (&a)[4],
                                     const uint32_t (&b)[2]) {
    asm volatile(
        "mma.sync.aligned.m16n8k32.row.col.s32.s8.s8.s32 "
        "{%0,%1,%2,%3}, {%4,%5,%6,%7}, {%8,%9}, {%0,%1,%2,%3};"
        : "+r"(d[0]), "+r"(d[1]), "+r"(d[2]), "+r"(d[3])
        : "r"(a[0]), "r"(a[1]), "r"(a[2]), "r"(a[3]), "r"(b[0]), "r"(b[1]));
}
#define CP_ASYNC(dst, src, n) \
    asm volatile("cp.async.cg.shared.global [%0], [%1], 16, %2;" \
                 :: "r"(dst), "l"(src), "r"(n) : "memory")
#define CP_COMMIT() asm volatile("cp.async.commit_group;" ::: "memory")
#define CP_WAIT0()  asm volatile("cp.async.wait_group 0;" ::: "memory")
#define STS128Z(a) \
    asm volatile("st.shared.v4.b32 [%0], {%1,%1,%1,%1};" :: "r"(a), "r"(0) : "memory")

// ---------------------------------------------------------------------------
// smem layout (all s8 act rows: 64B per pixel)
// ---------------------------------------------------------------------------
#define WS_OFF     0                         // 9 * 4096 = 36864
#define ACT_OFF    36864                     // 4 slots * 16512
#define SLOT_B     16512                     // 258 px * 64 B
#define INVS_OFF   (ACT_OFF + 4 * SLOT_B)    // 102912; 4 slots * 1056 B
#define INVS_SLOT  1056                      // pad4 + 256 + pad4 floats
#define BIAS_OFF   (INVS_OFF + 4 * INVS_SLOT)
#define SMEM_BYTES (BIAS_OFF + 256)          // ~107.5 KB

// ---------------------------------------------------------------------------
// Kernel 1 (R6): per-pixel LN + int8 quant -> s8 NHWC + inv_s
// ---------------------------------------------------------------------------
__global__ void __launch_bounds__(128) norm_quant_kernel(const float* __restrict__ x) {
    int p  = blockIdx.x * 128 + threadIdx.x;
    int b  = p >> 16;
    int sp = p & 65535;

    const float* xb = x + (size_t)b * 64 * 65536 + sp;

    float v[64];
    float sum = 0.f;
#pragma unroll
    for (int c = 0; c < 64; c++) { v[c] = xb[(size_t)c << 16]; sum += v[c]; }
    float mu = sum * (1.0f / 64.0f);

    float var = 0.f, mx = 0.f;
#pragma unroll
    for (int c = 0; c < 64; c++) {
        float d = v[c] - mu;
        var += d * d;
        mx = fmaxf(mx, fabsf(d));
    }
    var *= (1.0f / 64.0f);
    float r = rsqrtf(var + 1e-8f);

    float maxn  = fmaxf(mx * r, 1e-8f);
    float s     = 127.0f / maxn;
    float inv_s = maxn * (1.0f / 127.0f);

    unsigned char* yb = g_a8 + ((size_t)p << 6);
#pragma unroll
    for (int c4 = 0; c4 < 4; c4++) {
        uint4 wv;
        uint32_t wds[4];
#pragma unroll
        for (int jj = 0; jj < 4; jj++) {
            int ci = (c4 << 4) + (jj << 2);
            int q0 = (int)rintf(s * (r * (v[ci + 0] - mu)));
            int q1 = (int)rintf(s * (r * (v[ci + 1] - mu)));
            int q2 = (int)rintf(s * (r * (v[ci + 2] - mu)));
            int q3 = (int)rintf(s * (r * (v[ci + 3] - mu)));
            wds[jj] = (q0 & 255) | ((q1 & 255) << 8) | ((q2 & 255) << 16)
                    | ((q3 & 255) << 24);
        }
        wv.x = wds[0]; wv.y = wds[1]; wv.z = wds[2]; wv.w = wds[3];
        *(uint4*)(yb + (c4 << 4)) = wv;
    }
    g_invs[p] = inv_s;
}

// ---------------------------------------------------------------------------
// Kernel 2 (R6): ternary weight quant -> s8 [tap][co][ci]
// ---------------------------------------------------------------------------
__global__ void __launch_bounds__(512) wq_kernel(const float* __restrict__ Wt) {
    __shared__ float red[16];
    __shared__ float s_w_sh;
    int tid = threadIdx.x;

    float sum = 0.f;
    for (int i = tid; i < 36864; i += 512) sum += fabsf(Wt[i]);
#pragma unroll
    for (int o = 16; o; o >>= 1) sum += __shfl_xor_sync(0xffffffffu, sum, o);
    if ((tid & 31) == 0) red[tid >> 5] = sum;
    __syncthreads();
    if (tid < 32) {
        float s2 = (tid < 16) ? red[tid] : 0.f;
#pragma unroll
        for (int o = 8; o; o >>= 1) s2 += __shfl_xor_sync(0xffffffffu, s2, o);
        if (tid == 0) {
            float mean = s2 * (1.0f / 36864.0f);
            float inv_sw = fmaxf(mean, 1e-8f);
            s_w_sh = 1.0f / inv_sw;
            g_inv_sw = inv_sw;
        }
    }
    __syncthreads();
    float s_w = s_w_sh;

    for (int i = tid; i < 36864; i += 512) {
        float t = rintf(s_w * Wt[i]);
        t = fminf(fmaxf(t, -1.f), 1.f);
        int co  = i / 576;
        int rem = i - co * 576;
        int ci  = rem / 9;
        int tap = rem - ci * 9;
        g_w8[(tap * 64 + co) * 64 + ci] = (char)(int)t;
    }
}

// ---------------------------------------------------------------------------
// load one image row r (258 halo'd px x 64B s8) + its inv_s into ring slot r&3.
// s8 global byte: ((b<<16 | r<<8 | w) << 6) | c<<4; swizzle c ^ ((px>>1)&3)
// ---------------------------------------------------------------------------
__device__ __forceinline__ void load_row(uint32_t sb, int b, int r, int en, int tid) {
    if (!en) return;
    unsigned rok = ((unsigned)r < 256u) ? 1u : 0u;
    int rc = rok ? r : 0;
    size_t gbase = ((size_t)b << 16) | ((size_t)rc << 8);
    uint32_t slotb = sb + ACT_OFF + (uint32_t)(r & 3) * SLOT_B;
    for (int i = tid; i < 1032; i += 256) {          // 258 px * 4 chunks
        int px = i >> 2, c = i & 3;
        int w  = px - 1;
        unsigned ok = rok & (((unsigned)w < 256u) ? 1u : 0u);
        size_t off = ((gbase | (size_t)(ok ? w : 0)) << 6) | ((size_t)c << 4);
        uint32_t dst = slotb + (px << 6) + ((c ^ ((px >> 1) & 3)) << 4);
        CP_ASYNC(dst, (const char*)g_a8 + off, ok ? 16u : 0u);
    }
    if (tid < 64) {                                   // inv_s row: 256 floats
        uint32_t dst = sb + INVS_OFF + (uint32_t)(r & 3) * INVS_SLOT + 16 + (tid << 4);
        const char* src = (const char*)g_invs + ((gbase << 2) + ((size_t)tid << 4));
        CP_ASYNC(dst, src, rok ? 16u : 0u);
    }
}

// ---------------------------------------------------------------------------
// Kernel 3: conv. 256 threads, 8 warps; warp w -> out row h+(w&1),
// px [(w>>1)*64, +64) x 64 co. Per-tap IMMA + per-input-pixel scale.
// ---------------------------------------------------------------------------
__global__ void __launch_bounds__(256, 1) conv_kernel(const float* __restrict__ bias,
                                                      float* __restrict__ out) {
    extern __shared__ __align__(1024) unsigned char smem[];
    uint32_t sb = smem_u32(smem);
    int tid = threadIdx.x, wid = tid >> 5, lane = tid & 31;

    int s_ = blockIdx.x;                    // strip 0..18
    int b  = blockIdx.y;                    // image 0..7
    int p0 = (s_ < 14) ? 7 * s_ : 98 + 6 * (s_ - 14);
    int p1 = p0 + ((s_ < 14) ? 7 : 6);

    // ---- weights -> smem (R6 swizzle), bias, invs pads ----
    for (int i = tid; i < 2304; i += 256) {
        int tap = i >> 8;
        int rr  = i & 255;
        int co  = rr >> 2;
        int c   = rr & 3;
        uint32_t dst = sb + WS_OFF + (tap << 12) + (co << 6)
                     + ((c ^ ((co >> 1) & 3)) << 4);
        CP_ASYNC(dst, g_w8 + ((size_t)i << 4), 16u);
    }
    if (tid < 64) ((float*)(smem + BIAS_OFF))[tid] = bias[tid];
    if (tid < 8) {                           // zero inv_s slot pads
        int slot = tid & 3, hi = tid >> 2;
        STS128Z(sb + INVS_OFF + slot * INVS_SLOT + (hi ? 1040 : 0));
    }

    // ---- prologue: rows 2*p0-1 .. 2*p0+2 ----
    int h0 = 2 * p0;
#pragma unroll
    for (int rr = 0; rr < 4; rr++) load_row(sb, b, h0 - 1 + rr, 1, tid);
    CP_COMMIT();

    float inv_sw = g_inv_sw;

    // ---- per-thread ldmatrix geometry (R6-proven, s8/64B rows) ----
    int px0    = (wid >> 1) << 6;
    int ho_off = wid & 1;
    int l15 = lane & 15;
    int hi  = lane >> 4;
    int lb  = lane & 7;
    int b1  = (lane >> 3) & 1;
    uint32_t sB   = (uint32_t)((lb >> 1) & 3);
    uint32_t boff = (uint32_t)(lb << 6);
    uint32_t aoffs[3], sA[3];
#pragma unroll
    for (int kw = 0; kw < 3; kw++) {
        int pxk = px0 + kw + l15;
        aoffs[kw] = (uint32_t)(pxk << 6);
        sA[kw]    = (uint32_t)((pxk >> 1) & 3);
    }
    int qr = lane >> 2, qc = (lane & 3) << 1;

    float facc[4][8][4];

    // one (kh,kw) tap: fresh IMMA into s32 stage, scale into facc
    auto do_tap = [&](uint32_t slotb, const float* isl, int kw, int tap) {
        uint32_t wb = sb + WS_OFF + (tap << 12);
        uint32_t ab = slotb + aoffs[kw];
        // scales: input w = px0 + mt*16 + row + kw - 1; float idx = w + 4
        float sc[4][2];
#pragma unroll
        for (int mt = 0; mt < 4; mt++) {
            int fi = px0 + mt * 16 + qr + kw + 3;
            sc[mt][0] = isl[fi];
            sc[mt][1] = isl[fi + 8];
        }
        uint32_t A[2][4][4];
#pragma unroll
        for (int kk = 0; kk < 2; kk++)
#pragma unroll
            for (int mt = 0; mt < 4; mt++) {
                uint32_t ca = (uint32_t)((kk << 1) | hi) ^ sA[kw];
                ldsm_x4(A[kk][mt], ab + (uint32_t)(mt << 10) + (ca << 4));
            }
#pragma unroll
        for (int n = 0; n < 8; n++) {
            uint32_t B0[2], B1[2];
            uint32_t cb0 = (((uint32_t)b1) ^ sB) << 4;
            uint32_t cb1 = (((uint32_t)(2 | b1)) ^ sB) << 4;
            ldsm_x2(B0, wb + (n << 9) + boff + cb0);
            ldsm_x2(B1, wb + (n << 9) + boff + cb1);
            int st[4][4];
#pragma unroll
            for (int mt = 0; mt < 4; mt++) {
                imma_z(st[mt], A[0][mt], B0);
                imma(st[mt], A[1][mt], B1);
            }
#pragma unroll
            for (int mt = 0; mt < 4; mt++) {
                facc[mt][n][0] += (float)st[mt][0] * sc[mt][0];
                facc[mt][n][1] += (float)st[mt][1] * sc[mt][0];
                facc[mt][n][2] += (float)st[mt][2] * sc[mt][1];
                facc[mt][n][3] += (float)st[mt][3] * sc[mt][1];
            }
        }
    };

    auto do_phase = [&](int h, int kh) {
        int in_row = h + ho_off - 1 + kh;
        uint32_t slotb = sb + ACT_OFF + (uint32_t)(in_row & 3) * SLOT_B;
        const float* isl = (const float*)(smem + INVS_OFF + (in_row & 3) * INVS_SLOT);
#pragma unroll
        for (int kw = 0; kw < 3; kw++) do_tap(slotb, isl, kw, kh * 3 + kw);
    };

    for (int p = p0; p < p1; p++) {
        int h  = 2 * p;
        int en = (p + 1 < p1);

        CP_WAIT0();
        __syncthreads();

#pragma unroll
        for (int mt = 0; mt < 4; mt++)
#pragma unroll
            for (int n = 0; n < 8; n++)
#pragma unroll
                for (int e = 0; e < 4; e++) facc[mt][n][e] = 0.f;

        do_phase(h, 0);
        __syncthreads();                      // row h-1 dead
        load_row(sb, b, h + 3, en, tid);
        CP_COMMIT();

        do_phase(h, 1);
        __syncthreads();                      // row h dead
        load_row(sb, b, h + 4, en, tid);
        CP_COMMIT();

        do_phase(h, 2);

        // ---- epilogue: weight-scale + bias, fp32 NCHW ----
        const float* bs = (const float*)(smem + BIAS_OFF);
        int ho = h + ho_off;
        float* ob = out + ((size_t)b << 22) + ((size_t)ho << 8);
#pragma unroll
        for (int mt = 0; mt < 4; mt++) {
            int px = px0 + mt * 16 + qr;
#pragma unroll
            for (int n = 0; n < 8; n++) {
                int co = (n << 3) + qc;
                float bc0 = bs[co], bc1 = bs[co + 1];
                float* o0 = ob + ((size_t)co << 16) + px;
                float* o1 = ob + ((size_t)(co + 1) << 16) + px;
                o0[0] = facc[mt][n][0] * inv_sw + bc0;
                o1[0] = facc[mt][n][1] * inv_sw + bc1;
                o0[8] = facc[mt][n][2] * inv_sw + bc0;
                o1[8] = facc[mt][n][3] * inv_sw + bc1;
            }
        }
    }
    CP_WAIT0();
}

// ---------------------------------------------------------------------------
extern "C" void kernel_launch(void* const* d_in, const int* in_sizes, int n_in,
                              void* d_out, int out_size) {
    (void)in_sizes; (void)n_in; (void)out_size;
    const float* x    = (const float*)d_in[0];
    const float* Wt   = (const float*)d_in[1];
    const float* bias = (const float*)d_in[2];
    float* out = (float*)d_out;

    cudaFuncSetAttribute(conv_kernel, cudaFuncAttributeMaxDynamicSharedMemorySize,
                         SMEM_BYTES);

    norm_quant_kernel<<<8 * 65536 / 128, 128>>>(x);
    wq_kernel<<<1, 512>>>(Wt);
    dim3 grid(19, 8);
    conv_kernel<<<grid, 256, SMEM_BYTES>>>(bias, out);
}

// round 10
// speedup vs baseline: 1.0364x; 1.0364x over previous
#include <cuda_runtime.h>
#include <cstdint>
#include <math.h>

// ===========================================================================
// MMFConv2d sm_103a (base-target-safe), Round 10:
//   K1: per-pixel channel-LN + int8 quant -> s8 NHWC + fp32 inv_s (proven)
//   K2: ternary weight quant -> s8 [tap][co][ci] (proven)
//   K3: conv = 9 per-tap s8 IMMA GEMMs (m16n8k32, fresh s32 per tap),
//       per-input-pixel inv_s fold in fp32 (exact math, R9-proven),
//       NOW: 512 thr / 16 warps, 32px x 64co warp tiles (64-reg facc, no
//       spills), 4 warps/SMSP, R8-proven strip/row-ring/tap-phased prefetch.
// ===========================================================================

__device__ unsigned char g_a8[(size_t)8 * 65536 * 64];   // s8 NHWC
__device__ float g_invs[8 * 65536];                      // per-pixel inv_s
__device__ char  g_w8[9 * 64 * 64];                      // [tap][co][ci]
__device__ float g_inv_sw;

// ---------------------------------------------------------------------------
__device__ __forceinline__ uint32_t smem_u32(const void* p) {
    uint32_t a;
    asm("{ .reg .u64 t; cvta.to.shared.u64 t, %1; cvt.u32.u64 %0, t; }"
        : "=r"(a) : "l"(p));
    return a;
}
__device__ __forceinline__ void ldsm_x4(uint32_t (&r)[4], uint32_t a) {
    asm volatile("ldmatrix.sync.aligned.m8n8.x4.shared.b16 {%0,%1,%2,%3}, [%4];"
                 : "=r"(r[0]), "=r"(r[1]), "=r"(r[2]), "=r"(r[3]) : "r"(a));
}
__device__ __forceinline__ void ldsm_x2(uint32_t (&r)[2], uint32_t a) {
    asm volatile("ldmatrix.sync.aligned.m8n8.x2.shared.b16 {%0,%1}, [%2];"
                 : "=r"(r[0]), "=r"(r[1]) : "r"(a));
}
__device__ __forceinline__ void imma_z(int (&d)[4], const uint32_t (&a)[4],
                                       const uint32_t (&b)[2]) {
    asm volatile(
        "mma.sync.aligned.m16n8k32.row.col.s32.s8.s8.s32 "
        "{%0,%1,%2,%3}, {%4,%5,%6,%7}, {%8,%9}, {%10,%10,%10,%10};"
        : "=r"(d[0]), "=r"(d[1]), "=r"(d[2]), "=r"(d[3])
        : "r"(a[0]), "r"(a[1]), "r"(a[2]), "r"(a[3]), "r"(b[0]), "r"(b[1]),
          "r"(0));
}
__device__ __forceinline__ void imma(int (&d)[4], const uint32_t (&a)[4],
                                     const uint32_t (&b)[2]) {
    asm volatile(
        "mma.sync.aligned.m16n8k32.row.col.s32.s8.s8.s32 "
        "{%0,%1,%2,%3}, {%4,%5,%6,%7}, {%8,%9}, {%0,%1,%2,%3};"
        : "+r"(d[0]), "+r"(d[1]), "+r"(d[2]), "+r"(d[3])
        : "r"(a[0]), "r"(a[1]), "r"(a[2]), "r"(a[3]), "r"(b[0]), "r"(b[1]));
}
#define CP_ASYNC(dst, src, n) \
    asm volatile("cp.async.cg.shared.global [%0], [%1], 16, %2;" \
                 :: "r"(dst), "l"(src), "r"(n) : "memory")
#define CP_COMMIT() asm volatile("cp.async.commit_group;" ::: "memory")
#define CP_WAIT0()  asm volatile("cp.async.wait_group 0;" ::: "memory")
#define STS128Z(a) \
    asm volatile("st.shared.v4.b32 [%0], {%1,%1,%1,%1};" :: "r"(a), "r"(0) : "memory")

// ---------------------------------------------------------------------------
// smem layout (s8 act rows: 64B per pixel)
// ---------------------------------------------------------------------------
#define WS_OFF     0                         // 9 * 4096 = 36864
#define ACT_OFF    36864                     // 4 slots * 16512
#define SLOT_B     16512                     // 258 px * 64 B
#define INVS_OFF   (ACT_OFF + 4 * SLOT_B)    // 102912; 4 slots * 1056 B
#define INVS_SLOT  1056
#define BIAS_OFF   (INVS_OFF + 4 * INVS_SLOT)
#define SMEM_BYTES (BIAS_OFF + 256)          // ~107.5 KB

// ---------------------------------------------------------------------------
// Kernel 1 (proven): per-pixel LN + int8 quant -> s8 NHWC + inv_s
// ---------------------------------------------------------------------------
__global__ void __launch_bounds__(128) norm_quant_kernel(const float* __restrict__ x) {
    int p  = blockIdx.x * 128 + threadIdx.x;
    int b  = p >> 16;
    int sp = p & 65535;

    const float* xb = x + (size_t)b * 64 * 65536 + sp;

    float v[64];
    float sum = 0.f;
#pragma unroll
    for (int c = 0; c < 64; c++) { v[c] = xb[(size_t)c << 16]; sum += v[c]; }
    float mu = sum * (1.0f / 64.0f);

    float var = 0.f, mx = 0.f;
#pragma unroll
    for (int c = 0; c < 64; c++) {
        float d = v[c] - mu;
        var += d * d;
        mx = fmaxf(mx, fabsf(d));
    }
    var *= (1.0f / 64.0f);
    float r = rsqrtf(var + 1e-8f);

    float maxn  = fmaxf(mx * r, 1e-8f);
    float s     = 127.0f / maxn;
    float inv_s = maxn * (1.0f / 127.0f);

    unsigned char* yb = g_a8 + ((size_t)p << 6);
#pragma unroll
    for (int c4 = 0; c4 < 4; c4++) {
        uint4 wv;
        uint32_t wds[4];
#pragma unroll
        for (int jj = 0; jj < 4; jj++) {
            int ci = (c4 << 4) + (jj << 2);
            int q0 = (int)rintf(s * (r * (v[ci + 0] - mu)));
            int q1 = (int)rintf(s * (r * (v[ci + 1] - mu)));
            int q2 = (int)rintf(s * (r * (v[ci + 2] - mu)));
            int q3 = (int)rintf(s * (r * (v[ci + 3] - mu)));
            wds[jj] = (q0 & 255) | ((q1 & 255) << 8) | ((q2 & 255) << 16)
                    | ((q3 & 255) << 24);
        }
        wv.x = wds[0]; wv.y = wds[1]; wv.z = wds[2]; wv.w = wds[3];
        *(uint4*)(yb + (c4 << 4)) = wv;
    }
    g_invs[p] = inv_s;
}

// ---------------------------------------------------------------------------
// Kernel 2 (proven): ternary weight quant -> s8 [tap][co][ci]
// ---------------------------------------------------------------------------
__global__ void __launch_bounds__(512) wq_kernel(const float* __restrict__ Wt) {
    __shared__ float red[16];
    __shared__ float s_w_sh;
    int tid = threadIdx.x;

    float sum = 0.f;
    for (int i = tid; i < 36864; i += 512) sum += fabsf(Wt[i]);
#pragma unroll
    for (int o = 16; o; o >>= 1) sum += __shfl_xor_sync(0xffffffffu, sum, o);
    if ((tid & 31) == 0) red[tid >> 5] = sum;
    __syncthreads();
    if (tid < 32) {
        float s2 = (tid < 16) ? red[tid] : 0.f;
#pragma unroll
        for (int o = 8; o; o >>= 1) s2 += __shfl_xor_sync(0xffffffffu, s2, o);
        if (tid == 0) {
            float mean = s2 * (1.0f / 36864.0f);
            float inv_sw = fmaxf(mean, 1e-8f);
            s_w_sh = 1.0f / inv_sw;
            g_inv_sw = inv_sw;
        }
    }
    __syncthreads();
    float s_w = s_w_sh;

    for (int i = tid; i < 36864; i += 512) {
        float t = rintf(s_w * Wt[i]);
        t = fminf(fmaxf(t, -1.f), 1.f);
        int co  = i / 576;
        int rem = i - co * 576;
        int ci  = rem / 9;
        int tap = rem - ci * 9;
        g_w8[(tap * 64 + co) * 64 + ci] = (char)(int)t;
    }
}

// ---------------------------------------------------------------------------
// load one image row r (258 halo'd px x 64B s8) + inv_s into ring slot r&3.
// ---------------------------------------------------------------------------
__device__ __forceinline__ void load_row(uint32_t sb, int b, int r, int en, int tid) {
    if (!en) return;
    unsigned rok = ((unsigned)r < 256u) ? 1u : 0u;
    int rc = rok ? r : 0;
    size_t gbase = ((size_t)b << 16) | ((size_t)rc << 8);
    uint32_t slotb = sb + ACT_OFF + (uint32_t)(r & 3) * SLOT_B;
    for (int i = tid; i < 1032; i += 512) {          // 258 px * 4 chunks
        int px = i >> 2, c = i & 3;
        int w  = px - 1;
        unsigned ok = rok & (((unsigned)w < 256u) ? 1u : 0u);
        size_t off = ((gbase | (size_t)(ok ? w : 0)) << 6) | ((size_t)c << 4);
        uint32_t dst = slotb + (px << 6) + ((c ^ ((px >> 1) & 3)) << 4);
        CP_ASYNC(dst, (const char*)g_a8 + off, ok ? 16u : 0u);
    }
    if (tid < 64) {                                   // inv_s row: 256 floats
        uint32_t dst = sb + INVS_OFF + (uint32_t)(r & 3) * INVS_SLOT + 16 + (tid << 4);
        const char* src = (const char*)g_invs + ((gbase << 2) + ((size_t)tid << 4));
        CP_ASYNC(dst, src, rok ? 16u : 0u);
    }
}

// ---------------------------------------------------------------------------
// Kernel 3: conv. 512 threads, 16 warps; warp w -> out row h+(w&1),
// px [(w>>1)*32, +32) x 64 co. Per-tap IMMA + per-input-pixel scale fold.
// ---------------------------------------------------------------------------
__global__ void __launch_bounds__(512, 1) conv_kernel(const float* __restrict__ bias,
                                                      float* __restrict__ out) {
    extern __shared__ __align__(1024) unsigned char smem[];
    uint32_t sb = smem_u32(smem);
    int tid = threadIdx.x, wid = tid >> 5, lane = tid & 31;

    int s_ = blockIdx.x;                    // strip 0..18
    int b  = blockIdx.y;                    // image 0..7
    int p0 = (s_ < 14) ? 7 * s_ : 98 + 6 * (s_ - 14);
    int p1 = p0 + ((s_ < 14) ? 7 : 6);

    // ---- weights -> smem (proven swizzle), bias, invs pads ----
    for (int i = tid; i < 2304; i += 512) {
        int tap = i >> 8;
        int rr  = i & 255;
        int co  = rr >> 2;
        int c   = rr & 3;
        uint32_t dst = sb + WS_OFF + (tap << 12) + (co << 6)
                     + ((c ^ ((co >> 1) & 3)) << 4);
        CP_ASYNC(dst, g_w8 + ((size_t)i << 4), 16u);
    }
    if (tid < 64) ((float*)(smem + BIAS_OFF))[tid] = bias[tid];
    if (tid < 8) {
        int slot = tid & 3, hi2 = tid >> 2;
        STS128Z(sb + INVS_OFF + slot * INVS_SLOT + (hi2 ? 1040 : 0));
    }

    // ---- prologue ----
    int h0 = 2 * p0;
#pragma unroll
    for (int rr = 0; rr < 4; rr++) load_row(sb, b, h0 - 1 + rr, 1, tid);
    CP_COMMIT();

    float inv_sw = g_inv_sw;

    // ---- per-thread ldmatrix geometry (R9-proven, s8/64B rows) ----
    int px0    = (wid >> 1) << 5;           // 32-px column block
    int ho_off = wid & 1;
    int l15 = lane & 15;
    int hi  = lane >> 4;
    int lb  = lane & 7;
    int b1  = (lane >> 3) & 1;
    uint32_t sB   = (uint32_t)((lb >> 1) & 3);
    uint32_t boff = (uint32_t)(lb << 6);
    uint32_t aoffs[3], sA[3];
#pragma unroll
    for (int kw = 0; kw < 3; kw++) {
        int pxk = px0 + kw + l15;
        aoffs[kw] = (uint32_t)(pxk << 6);
        sA[kw]    = (uint32_t)((pxk >> 1) & 3);
    }
    int qr = lane >> 2, qc = (lane & 3) << 1;

    float facc[2][8][4];

    auto do_tap = [&](uint32_t slotb, const float* isl, int kw, int tap) {
        uint32_t wb = sb + WS_OFF + (tap << 12);
        uint32_t ab = slotb + aoffs[kw];
        float sc[2][2];
#pragma unroll
        for (int mt = 0; mt < 2; mt++) {
            int fi = px0 + mt * 16 + qr + kw + 3;    // input px + 4 (slot pad)
            sc[mt][0] = isl[fi];
            sc[mt][1] = isl[fi + 8];
        }
        uint32_t A[2][2][4];                         // [kk][mt]
#pragma unroll
        for (int kk = 0; kk < 2; kk++)
#pragma unroll
            for (int mt = 0; mt < 2; mt++) {
                uint32_t ca = (uint32_t)((kk << 1) | hi) ^ sA[kw];
                ldsm_x4(A[kk][mt], ab + (uint32_t)(mt << 10) + (ca << 4));
            }
        uint32_t cb0 = (((uint32_t)b1) ^ sB) << 4;
        uint32_t cb1 = (((uint32_t)(2 | b1)) ^ sB) << 4;
#pragma unroll
        for (int n = 0; n < 8; n++) {
            uint32_t B0[2], B1[2];
            ldsm_x2(B0, wb + (n << 9) + boff + cb0);
            ldsm_x2(B1, wb + (n << 9) + boff + cb1);
#pragma unroll
            for (int mt = 0; mt < 2; mt++) {
                int st[4];
                imma_z(st, A[0][mt], B0);
                imma(st, A[1][mt], B1);
                facc[mt][n][0] += (float)st[0] * sc[mt][0];
                facc[mt][n][1] += (float)st[1] * sc[mt][0];
                facc[mt][n][2] += (float)st[2] * sc[mt][1];
                facc[mt][n][3] += (float)st[3] * sc[mt][1];
            }
        }
    };

    auto do_phase = [&](int h, int kh) {
        int in_row = h + ho_off - 1 + kh;
        uint32_t slotb = sb + ACT_OFF + (uint32_t)(in_row & 3) * SLOT_B;
        const float* isl = (const float*)(smem + INVS_OFF + (in_row & 3) * INVS_SLOT);
#pragma unroll
        for (int kw = 0; kw < 3; kw++) do_tap(slotb, isl, kw, kh * 3 + kw);
    };

    for (int p = p0; p < p1; p++) {
        int h  = 2 * p;
        int en = (p + 1 < p1);

        CP_WAIT0();
        __syncthreads();

#pragma unroll
        for (int mt = 0; mt < 2; mt++)
#pragma unroll
            for (int n = 0; n < 8; n++)
#pragma unroll
                for (int e = 0; e < 4; e++) facc[mt][n][e] = 0.f;

        do_phase(h, 0);
        __syncthreads();                      // row h-1 dead
        load_row(sb, b, h + 3, en, tid);
        CP_COMMIT();

        do_phase(h, 1);
        __syncthreads();                      // row h dead
        load_row(sb, b, h + 4, en, tid);
        CP_COMMIT();

        do_phase(h, 2);

        // ---- epilogue: weight-scale + bias, fp32 NCHW ----
        const float* bs = (const float*)(smem + BIAS_OFF);
        int ho = h + ho_off;
        float* ob = out + ((size_t)b << 22) + ((size_t)ho << 8);
#pragma unroll
        for (int mt = 0; mt < 2; mt++) {
            int px = px0 + mt * 16 + qr;
#pragma unroll
            for (int n = 0; n < 8; n++) {
                int co = (n << 3) + qc;
                float bc0 = bs[co], bc1 = bs[co + 1];
                float* o0 = ob + ((size_t)co << 16) + px;
                float* o1 = ob + ((size_t)(co + 1) << 16) + px;
                o0[0] = facc[mt][n][0] * inv_sw + bc0;
                o1[0] = facc[mt][n][1] * inv_sw + bc1;
                o0[8] = facc[mt][n][2] * inv_sw + bc0;
                o1[8] = facc[mt][n][3] * inv_sw + bc1;
            }
        }
    }
    CP_WAIT0();
}

// ---------------------------------------------------------------------------
extern "C" void kernel_launch(void* const* d_in, const int* in_sizes, int n_in,
                              void* d_out, int out_size) {
    (void)in_sizes; (void)n_in; (void)out_size;
    const float* x    = (const float*)d_in[0];
    const float* Wt   = (const float*)d_in[1];
    const float* bias = (const float*)d_in[2];
    float* out = (float*)d_out;

    cudaFuncSetAttribute(conv_kernel, cudaFuncAttributeMaxDynamicSharedMemorySize,
                         SMEM_BYTES);

    norm_quant_kernel<<<8 * 65536 / 128, 128>>>(x);
    wq_kernel<<<1, 512>>>(Wt);
    dim3 grid(19, 8);
    conv_kernel<<<grid, 512, SMEM_BYTES>>>(bias, out);
}

// round 11
// speedup vs baseline: 2.2413x; 2.1626x over previous
#include <cuda_runtime.h>
#include <cuda_fp16.h>
#include <cstdint>
#include <math.h>

// ===========================================================================
// MMFConv2d sm_103a (base-target-safe), Round 11:
//   R8 (154.6us best) with the conv retiled to 512 thr / 16 warps
//   (4 warps/SMSP): warp = 32px x 64co, same row-pair tile, same proven
//   ring/prefetch/swizzle/fragments. Probes HMMA issue saturation.
// ===========================================================================

__device__ __half g_a[(size_t)8 * 65536 * 64];   // fp16 NHWC activations
__device__ __half g_w[9 * 64 * 64];              // fp16 ternary weights
__device__ float g_inv_sw;

// ---------------------------------------------------------------------------
__device__ __forceinline__ uint32_t smem_u32(const void* p) {
    uint32_t a;
    asm("{ .reg .u64 t; cvta.to.shared.u64 t, %1; cvt.u32.u64 %0, t; }"
        : "=r"(a) : "l"(p));
    return a;
}
__device__ __forceinline__ void ldsm_x4(uint32_t (&r)[4], uint32_t a) {
    asm volatile("ldmatrix.sync.aligned.m8n8.x4.shared.b16 {%0,%1,%2,%3}, [%4];"
                 : "=r"(r[0]), "=r"(r[1]), "=r"(r[2]), "=r"(r[3]) : "r"(a));
}
__device__ __forceinline__ void ldsm_x2(uint32_t (&r)[2], uint32_t a) {
    asm volatile("ldmatrix.sync.aligned.m8n8.x2.shared.b16 {%0,%1}, [%2];"
                 : "=r"(r[0]), "=r"(r[1]) : "r"(a));
}
__device__ __forceinline__ void mma16816(float (&d)[4], const uint32_t (&a)[4],
                                         const uint32_t (&b)[2]) {
    asm volatile(
        "mma.sync.aligned.m16n8k16.row.col.f32.f16.f16.f32 "
        "{%0,%1,%2,%3}, {%4,%5,%6,%7}, {%8,%9}, {%0,%1,%2,%3};"
        : "+f"(d[0]), "+f"(d[1]), "+f"(d[2]), "+f"(d[3])
        : "r"(a[0]), "r"(a[1]), "r"(a[2]), "r"(a[3]), "r"(b[0]), "r"(b[1]));
}
#define CP_ASYNC(dst, src, n) \
    asm volatile("cp.async.cg.shared.global [%0], [%1], 16, %2;" \
                 :: "r"(dst), "l"(src), "r"(n) : "memory")
#define CP_COMMIT() asm volatile("cp.async.commit_group;" ::: "memory")
#define CP_WAIT0()  asm volatile("cp.async.wait_group 0;" ::: "memory")

// ---------------------------------------------------------------------------
// smem layout
// ---------------------------------------------------------------------------
#define WS_OFF     0                        // 9 * 8192 = 73728
#define ACT_OFF    73728                    // 4 row slots * 33024
#define SLOT_B     33024                    // 258 px * 128 B
#define BIAS_OFF   (ACT_OFF + 4 * SLOT_B)   // 205824
#define SMEM_BYTES (BIAS_OFF + 256)         // 206080

// ---------------------------------------------------------------------------
// Kernel 1 (proven): per-pixel LN + int8 fake-quant -> fp16 NHWC
// ---------------------------------------------------------------------------
__global__ void __launch_bounds__(128) norm_quant_kernel(const float* __restrict__ x) {
    int p  = blockIdx.x * 128 + threadIdx.x;
    int b  = p >> 16;
    int sp = p & 65535;

    const float* xb = x + (size_t)b * 64 * 65536 + sp;

    float v[64];
    float sum = 0.f;
#pragma unroll
    for (int c = 0; c < 64; c++) { v[c] = xb[(size_t)c << 16]; sum += v[c]; }
    float mu = sum * (1.0f / 64.0f);

    float var = 0.f, mx = 0.f;
#pragma unroll
    for (int c = 0; c < 64; c++) {
        float d = v[c] - mu;
        var += d * d;
        mx = fmaxf(mx, fabsf(d));
    }
    var *= (1.0f / 64.0f);
    float r = rsqrtf(var + 1e-8f);

    float maxn  = fmaxf(mx * r, 1e-8f);
    float s     = 127.0f / maxn;
    float inv_s = maxn * (1.0f / 127.0f);

    __half* yb = g_a + ((size_t)p << 6);
#pragma unroll
    for (int c = 0; c < 64; c += 8) {
        uint4 u;
        __half2 h2;
        float q0, q1;
#define QV(cc) fminf(fmaxf(rintf(s * (r * (v[cc] - mu))), -128.f), 127.f) * inv_s
        q0 = QV(c + 0); q1 = QV(c + 1); h2 = __floats2half2_rn(q0, q1); u.x = *(uint32_t*)&h2;
        q0 = QV(c + 2); q1 = QV(c + 3); h2 = __floats2half2_rn(q0, q1); u.y = *(uint32_t*)&h2;
        q0 = QV(c + 4); q1 = QV(c + 5); h2 = __floats2half2_rn(q0, q1); u.z = *(uint32_t*)&h2;
        q0 = QV(c + 6); q1 = QV(c + 7); h2 = __floats2half2_rn(q0, q1); u.w = *(uint32_t*)&h2;
#undef QV
        *(uint4*)(yb + c) = u;
    }
}

// ---------------------------------------------------------------------------
// Kernel 2 (proven): ternary weight quant -> exact fp16 [tap][co][ci]
// ---------------------------------------------------------------------------
__global__ void __launch_bounds__(512) wq_kernel(const float* __restrict__ Wt) {
    __shared__ float red[16];
    __shared__ float s_w_sh;
    int tid = threadIdx.x;

    float sum = 0.f;
    for (int i = tid; i < 36864; i += 512) sum += fabsf(Wt[i]);
#pragma unroll
    for (int o = 16; o; o >>= 1) sum += __shfl_xor_sync(0xffffffffu, sum, o);
    if ((tid & 31) == 0) red[tid >> 5] = sum;
    __syncthreads();
    if (tid < 32) {
        float s2 = (tid < 16) ? red[tid] : 0.f;
#pragma unroll
        for (int o = 8; o; o >>= 1) s2 += __shfl_xor_sync(0xffffffffu, s2, o);
        if (tid == 0) {
            float mean = s2 * (1.0f / 36864.0f);
            float inv_sw = fmaxf(mean, 1e-8f);
            s_w_sh = 1.0f / inv_sw;
            g_inv_sw = inv_sw;
        }
    }
    __syncthreads();
    float s_w = s_w_sh;

    for (int i = tid; i < 36864; i += 512) {
        float t = rintf(s_w * Wt[i]);
        t = fminf(fmaxf(t, -1.f), 1.f);
        int co  = i / 576;
        int rem = i - co * 576;
        int ci  = rem / 9;
        int tap = rem - ci * 9;
        g_w[(tap * 64 + co) * 64 + ci] = __float2half_rn(t);   // exact
    }
}

// ---------------------------------------------------------------------------
// load one image row r (258 halo'd px x 128B fp16) into ring slot r&3.
// ---------------------------------------------------------------------------
__device__ __forceinline__ void load_row(uint32_t sb, int b, int r, int en, int tid) {
    if (!en) return;
    unsigned rok = ((unsigned)r < 256u) ? 1u : 0u;
    int rc = rok ? r : 0;
    size_t gbase = ((size_t)b << 16) | ((size_t)rc << 8);
    uint32_t slotb = sb + ACT_OFF + (uint32_t)(r & 3) * SLOT_B;
    for (int i = tid; i < 2064; i += 512) {         // 258 px * 8 chunks
        int loc = i >> 3, c = i & 7;
        int w   = loc - 1;
        unsigned ok = rok & (((unsigned)w < 256u) ? 1u : 0u);
        size_t off = ((gbase | (size_t)(ok ? w : 0)) << 7) | ((size_t)c << 4);
        uint32_t dst = slotb + (loc << 7) + ((c ^ (loc & 7)) << 4);
        CP_ASYNC(dst, (const char*)g_a + off, ok ? 16u : 0u);
    }
}

// ---------------------------------------------------------------------------
// Kernel 3: conv. 512 threads, 16 warps; warp w -> out row h+(w&1),
// px [(w>>1)*32, +32) x all 64 co. Strip of row-pairs, 4-slot row ring.
// ---------------------------------------------------------------------------
__global__ void __launch_bounds__(512, 1) conv_kernel(const float* __restrict__ bias,
                                                      float* __restrict__ out) {
    extern __shared__ __align__(1024) unsigned char smem[];
    uint32_t sb = smem_u32(smem);
    int tid = threadIdx.x, wid = tid >> 5, lane = tid & 31;

    int s_ = blockIdx.x;                    // strip 0..18
    int b  = blockIdx.y;                    // image 0..7
    int p0 = (s_ < 14) ? 7 * s_ : 98 + 6 * (s_ - 14);
    int p1 = p0 + ((s_ < 14) ? 7 : 6);      // row-pair range

    // ---- weights -> smem (proven swizzle), bias ----
    for (int i = tid; i < 4608; i += 512) {
        int tap = i >> 9;
        int r   = i & 511;
        int co  = r >> 3;
        int c   = r & 7;
        uint32_t dst = sb + WS_OFF + (tap << 13) + (co << 7) + ((c ^ (co & 7)) << 4);
        CP_ASYNC(dst, (const char*)g_w + ((size_t)i << 4), 16u);
    }
    if (tid < 64) ((float*)(smem + BIAS_OFF))[tid] = bias[tid];

    // ---- prologue: rows 2*p0-1 .. 2*p0+2 into the 4 ring slots ----
    int h0 = 2 * p0;
#pragma unroll
    for (int rr = 0; rr < 4; rr++) load_row(sb, b, h0 - 1 + rr, 1, tid);
    CP_COMMIT();

    float inv_sw = g_inv_sw;

    // ---- per-thread ldmatrix geometry (proven) ----
    int px0    = (wid >> 1) << 5;           // 32-px column block (0..224)
    int ho_off = wid & 1;
    int rA   = lane & 15;
    int colA = lane & 16;
    int rB   = lane & 7;
    int colB = ((lane >> 3) & 1) << 4;
    uint32_t rowBterm = (uint32_t)(rB << 7);
    uint32_t cxB = (uint32_t)(colB ^ (rB << 4));
    uint32_t rowbaseA[3], cxA[3];
#pragma unroll
    for (int kw = 0; kw < 3; kw++) {
        rowbaseA[kw] = (uint32_t)((px0 + kw + rA) << 7);
        cxA[kw]      = (uint32_t)(colA ^ (((kw + rA) & 7) << 4));
    }
    int qr = lane >> 2, qc = (lane & 3) << 1;

    float acc[2][8][4];

    auto do_phase = [&](int h, int kh) {
        int in_row = h + ho_off - 1 + kh;
        uint32_t slotb = sb + ACT_OFF + (uint32_t)(in_row & 3) * SLOT_B;
#pragma unroll
        for (int kw = 0; kw < 3; kw++) {
            int tap = kh * 3 + kw;
            uint32_t wb  = sb + WS_OFF + (tap << 13) + rowBterm;
            uint32_t ab  = slotb + rowbaseA[kw];
            uint32_t cxa = cxA[kw];
#pragma unroll
            for (int kk = 0; kk < 4; kk++) {
                uint32_t a[2][4];
#pragma unroll
                for (int mt = 0; mt < 2; mt++)
                    ldsm_x4(a[mt], ab + mt * 2048 + (((uint32_t)kk << 5) ^ cxa));
                uint32_t kB = ((uint32_t)kk << 5) ^ cxB;
#pragma unroll
                for (int n = 0; n < 8; n++) {
                    uint32_t bf[2];
                    ldsm_x2(bf, wb + ((uint32_t)n << 10) + kB);
#pragma unroll
                    for (int mt = 0; mt < 2; mt++)
                        mma16816(acc[mt][n], a[mt], bf);
                }
            }
        }
    };

    for (int p = p0; p < p1; p++) {
        int h  = 2 * p;
        int en = (p + 1 < p1);

        CP_WAIT0();
        __syncthreads();                       // all prefetched rows visible

#pragma unroll
        for (int mt = 0; mt < 2; mt++)
#pragma unroll
            for (int n = 0; n < 8; n++)
#pragma unroll
                for (int e = 0; e < 4; e++) acc[mt][n][e] = 0.f;

        do_phase(h, 0);                        // reads rows h-1, h
        __syncthreads();                       // row h-1 now dead
        load_row(sb, b, h + 3, en, tid);
        CP_COMMIT();

        do_phase(h, 1);                        // reads rows h, h+1
        __syncthreads();                       // row h now dead
        load_row(sb, b, h + 4, en, tid);
        CP_COMMIT();

        do_phase(h, 2);                        // reads rows h+1, h+2

        // ---- epilogue: weight-scale + bias, fp32 NCHW ----
        const float* bs = (const float*)(smem + BIAS_OFF);
        int ho = h + ho_off;
        float* ob = out + ((size_t)b << 22) + ((size_t)ho << 8);
#pragma unroll
        for (int mt = 0; mt < 2; mt++) {
            int px = px0 + mt * 16 + qr;
#pragma unroll
            for (int n = 0; n < 8; n++) {
                int co = (n << 3) + qc;
                float bc0 = bs[co], bc1 = bs[co + 1];
                float* o0 = ob + ((size_t)co << 16) + px;
                float* o1 = ob + ((size_t)(co + 1) << 16) + px;
                o0[0] = acc[mt][n][0] * inv_sw + bc0;
                o1[0] = acc[mt][n][1] * inv_sw + bc1;
                o0[8] = acc[mt][n][2] * inv_sw + bc0;
                o1[8] = acc[mt][n][3] * inv_sw + bc1;
            }
        }
    }
    CP_WAIT0();
}

// ---------------------------------------------------------------------------
extern "C" void kernel_launch(void* const* d_in, const int* in_sizes, int n_in,
                              void* d_out, int out_size) {
    (void)in_sizes; (void)n_in; (void)out_size;
    const float* x    = (const float*)d_in[0];
    const float* Wt   = (const float*)d_in[1];
    const float* bias = (const float*)d_in[2];
    float* out = (float*)d_out;

    cudaFuncSetAttribute(conv_kernel, cudaFuncAttributeMaxDynamicSharedMemorySize,
                         SMEM_BYTES);

    norm_quant_kernel<<<8 * 65536 / 128, 128>>>(x);
    wq_kernel<<<1, 512>>>(Wt);
    dim3 grid(19, 8);
    conv_kernel<<<grid, 512, SMEM_BYTES>>>(bias, out);
}